// round 1
// baseline (speedup 1.0000x reference)
#include <cuda_runtime.h>
#include <cuda_bf16.h>
#include <math.h>

// Problem constants
#define S 4096
#define H 2048
#define NH 16
#define HD 128
#define SCALE 0.08838834764831845f   // 1/sqrt(128)

// ---------------------------------------------------------------------------
// Scratch (device globals — allocation-free per harness rules)
// ---------------------------------------------------------------------------
__device__ float g_Q[S * H];
__device__ float g_K[S * H];
__device__ float g_V[S * H];
__device__ float g_O[S * H];

// ---------------------------------------------------------------------------
// SGEMM (NT): C[m][n] = sum_k A[m][k] * B[n][k] + bias[n]
// A: [M,K] row-major, B: [N,K] row-major (i.e. torch Linear weight), both
// K-contiguous. BM=BN=128, BK=16, 256 threads, 8x8 microtile.
// ---------------------------------------------------------------------------
#define GBM 128
#define GBN 128
#define GBK 16
#define GTM 8
#define GTN 8
#define GPAD 4

__global__ __launch_bounds__(256) void gemm_nt_bias(
    const float* __restrict__ A, const float* __restrict__ B,
    const float* __restrict__ bias, float* __restrict__ C,
    int M, int N, int K)
{
    __shared__ float As[GBK][GBM + GPAD];
    __shared__ float Bs[GBK][GBN + GPAD];

    const int tid = threadIdx.x;
    const int bm = blockIdx.y * GBM;
    const int bn = blockIdx.x * GBN;
    const int tx = tid & 15;        // 0..15  -> N direction
    const int ty = tid >> 4;        // 0..15  -> M direction

    float acc[GTM][GTN];
#pragma unroll
    for (int i = 0; i < GTM; i++)
#pragma unroll
        for (int j = 0; j < GTN; j++) acc[i][j] = 0.f;

    for (int k0 = 0; k0 < K; k0 += GBK) {
        // Load A tile: 128x16 floats = 512 float4, 2 per thread
#pragma unroll
        for (int it = 0; it < 2; it++) {
            int i4 = tid + it * 256;          // 0..511
            int r  = i4 >> 2;                 // 0..127
            int c  = (i4 & 3) << 2;           // 0,4,8,12
            float4 v = *(const float4*)&A[(size_t)(bm + r) * K + k0 + c];
            As[c + 0][r] = v.x; As[c + 1][r] = v.y;
            As[c + 2][r] = v.z; As[c + 3][r] = v.w;
        }
        // Load B tile
#pragma unroll
        for (int it = 0; it < 2; it++) {
            int i4 = tid + it * 256;
            int r  = i4 >> 2;
            int c  = (i4 & 3) << 2;
            float4 v = *(const float4*)&B[(size_t)(bn + r) * K + k0 + c];
            Bs[c + 0][r] = v.x; Bs[c + 1][r] = v.y;
            Bs[c + 2][r] = v.z; Bs[c + 3][r] = v.w;
        }
        __syncthreads();

#pragma unroll
        for (int kk = 0; kk < GBK; kk++) {
            float a[GTM], b[GTN];
#pragma unroll
            for (int i = 0; i < GTM; i++) a[i] = As[kk][ty * GTM + i];
#pragma unroll
            for (int j = 0; j < GTN; j++) b[j] = Bs[kk][tx * GTN + j];
#pragma unroll
            for (int i = 0; i < GTM; i++)
#pragma unroll
                for (int j = 0; j < GTN; j++)
                    acc[i][j] = fmaf(a[i], b[j], acc[i][j]);
        }
        __syncthreads();
    }

    // Epilogue: add bias, store (two float4 per row of the microtile)
#pragma unroll
    for (int i = 0; i < GTM; i++) {
        int m = bm + ty * GTM + i;
        int n0 = bn + tx * GTN;
#pragma unroll
        for (int j = 0; j < GTN; j += 4) {
            float4 o;
            o.x = acc[i][j + 0] + bias[n0 + j + 0];
            o.y = acc[i][j + 1] + bias[n0 + j + 1];
            o.z = acc[i][j + 2] + bias[n0 + j + 2];
            o.w = acc[i][j + 3] + bias[n0 + j + 3];
            *(float4*)&C[(size_t)m * N + n0 + j] = o;
        }
    }
}

// ---------------------------------------------------------------------------
// Flash attention, fp32.
// Grid: (S/AM, NH). Block: 256 threads.
// Each CTA: 64 query rows of one head. Loops over 64-key tiles.
// Thread t: row = t/4 (0..63), colgroup cg = t%4 -> owns output dims
// [cg*32, cg*32+32). Softmax state (m, l) held redundantly by the 4 threads
// of a row (identical arithmetic -> identical values).
// ---------------------------------------------------------------------------
#define AM 64
#define AN 64
#define APAD 4
#define AST (HD + APAD)   // 132 floats stride -> conflict-free

__global__ __launch_bounds__(256) void flash_attn_kernel(
    const float* __restrict__ Q, const float* __restrict__ K,
    const float* __restrict__ V, float* __restrict__ O)
{
    extern __shared__ float sm[];
    float* Qs = sm;                    // AM * AST
    float* Ks = Qs + AM * AST;         // AN * AST
    float* Vs = Ks + AN * AST;         // AN * AST
    float* Ss = Vs + AN * AST;         // AM * AN

    const int tid   = threadIdx.x;
    const int h     = blockIdx.y;
    const int qbase = blockIdx.x * AM;
    const int row   = tid >> 2;
    const int cg    = tid & 3;
    const size_t headoff = (size_t)h * HD;

    // Load Q tile (pre-scaled)
    for (int i = tid; i < AM * (HD / 4); i += 256) {
        int r = i / (HD / 4);
        int c = (i % (HD / 4)) * 4;
        float4 v = *(const float4*)&Q[(size_t)(qbase + r) * H + headoff + c];
        Qs[r * AST + c + 0] = v.x * SCALE;
        Qs[r * AST + c + 1] = v.y * SCALE;
        Qs[r * AST + c + 2] = v.z * SCALE;
        Qs[r * AST + c + 3] = v.w * SCALE;
    }

    float m_i = -INFINITY, l_i = 0.f;
    float acc[32];
#pragma unroll
    for (int c = 0; c < 32; c++) acc[c] = 0.f;

    for (int kb = 0; kb < S; kb += AN) {
        __syncthreads();   // prior-iter reads of Ks/Vs done (covers Q load too)

        // Load K and V tiles
        for (int i = tid; i < AN * (HD / 4); i += 256) {
            int r = i / (HD / 4);
            int c = (i % (HD / 4)) * 4;
            float4 kv = *(const float4*)&K[(size_t)(kb + r) * H + headoff + c];
            Ks[r * AST + c + 0] = kv.x; Ks[r * AST + c + 1] = kv.y;
            Ks[r * AST + c + 2] = kv.z; Ks[r * AST + c + 3] = kv.w;
            float4 vv = *(const float4*)&V[(size_t)(kb + r) * H + headoff + c];
            Vs[r * AST + c + 0] = vv.x; Vs[r * AST + c + 1] = vv.y;
            Vs[r * AST + c + 2] = vv.z; Vs[r * AST + c + 3] = vv.w;
        }
        __syncthreads();

        // Scores: each thread computes 16 keys for its row
        const float* qp = &Qs[row * AST];
#pragma unroll 1
        for (int kk = 0; kk < 16; kk++) {
            int key = cg * 16 + kk;
            const float* kp = &Ks[key * AST];
            float s = 0.f;
#pragma unroll
            for (int d = 0; d < HD; d += 4) {
                s = fmaf(qp[d + 0], kp[d + 0], s);
                s = fmaf(qp[d + 1], kp[d + 1], s);
                s = fmaf(qp[d + 2], kp[d + 2], s);
                s = fmaf(qp[d + 3], kp[d + 3], s);
            }
            Ss[row * AN + key] = s;
        }
        __syncthreads();

        // Online softmax + PV accumulate
        const float* srow = &Ss[row * AN];
        float m_new = m_i;
#pragma unroll
        for (int k = 0; k < AN; k++) m_new = fmaxf(m_new, srow[k]);
        float corr = __expf(m_i - m_new);
        l_i *= corr;
#pragma unroll
        for (int c = 0; c < 32; c++) acc[c] *= corr;
        m_i = m_new;

#pragma unroll 1
        for (int k = 0; k < AN; k++) {
            float p = __expf(srow[k] - m_i);
            l_i += p;
            const float* vp = &Vs[k * AST + cg * 32];
#pragma unroll
            for (int c = 0; c < 32; c++)
                acc[c] = fmaf(p, vp[c], acc[c]);
        }
    }

    // Write context: O[s][h*HD + d]
    float inv = 1.f / l_i;
    float* op = &O[(size_t)(qbase + row) * H + headoff + cg * 32];
#pragma unroll
    for (int c = 0; c < 32; c += 4) {
        float4 o;
        o.x = acc[c + 0] * inv; o.y = acc[c + 1] * inv;
        o.z = acc[c + 2] * inv; o.w = acc[c + 3] * inv;
        *(float4*)&op[c] = o;
    }
}

// ---------------------------------------------------------------------------
// Launch
// ---------------------------------------------------------------------------
extern "C" void kernel_launch(void* const* d_in, const int* in_sizes, int n_in,
                              void* d_out, int out_size)
{
    const float* hidden = (const float*)d_in[0];
    const float* Wq = (const float*)d_in[1];
    const float* bq = (const float*)d_in[2];
    const float* Wk = (const float*)d_in[3];
    const float* bk = (const float*)d_in[4];
    const float* Wv = (const float*)d_in[5];
    const float* bv = (const float*)d_in[6];
    const float* Wo = (const float*)d_in[7];
    const float* bo = (const float*)d_in[8];
    float* out = (float*)d_out;

    float *Qp, *Kp, *Vp, *Op;
    cudaGetSymbolAddress((void**)&Qp, g_Q);
    cudaGetSymbolAddress((void**)&Kp, g_K);
    cudaGetSymbolAddress((void**)&Vp, g_V);
    cudaGetSymbolAddress((void**)&Op, g_O);

    // Flash attention smem: (64+64+64)*132 + 64*64 floats
    const int attn_smem = (int)(((AM + 2 * AN) * AST + AM * AN) * sizeof(float));
    cudaFuncSetAttribute(flash_attn_kernel,
                         cudaFuncAttributeMaxDynamicSharedMemorySize, attn_smem);

    dim3 ggrid(H / GBN, S / GBM);   // (16, 32)
    dim3 gblk(256);

    gemm_nt_bias<<<ggrid, gblk>>>(hidden, Wq, bq, Qp, S, H, H);
    gemm_nt_bias<<<ggrid, gblk>>>(hidden, Wk, bk, Kp, S, H, H);
    gemm_nt_bias<<<ggrid, gblk>>>(hidden, Wv, bv, Vp, S, H, H);

    dim3 agrid(S / AM, NH);         // (64, 16)
    flash_attn_kernel<<<agrid, 256, attn_smem>>>(Qp, Kp, Vp, Op);

    gemm_nt_bias<<<ggrid, gblk>>>(Op, Wo, bo, out, S, H, H);
}

// round 2
// speedup vs baseline: 3.8081x; 3.8081x over previous
#include <cuda_runtime.h>
#include <cuda_bf16.h>
#include <math.h>

// Problem constants
#define S 4096
#define H 2048
#define NH 16
#define HD 128
#define SCALE 0.08838834764831845f   // 1/sqrt(128)

// ---------------------------------------------------------------------------
// Scratch (device globals — allocation-free per harness rules)
// ---------------------------------------------------------------------------
__device__ float g_Q[S * H];
__device__ float g_K[S * H];
__device__ float g_V[S * H];
__device__ float g_O[S * H];

// ---------------------------------------------------------------------------
// SGEMM (NT): C[m][n] = sum_k A[m][k] * B[n][k] + bias[n]
// ---------------------------------------------------------------------------
#define GBM 128
#define GBN 128
#define GBK 16
#define GTM 8
#define GTN 8
#define GPAD 4

__global__ __launch_bounds__(256) void gemm_nt_bias(
    const float* __restrict__ A, const float* __restrict__ B,
    const float* __restrict__ bias, float* __restrict__ C,
    int M, int N, int K)
{
    __shared__ float As[GBK][GBM + GPAD];
    __shared__ float Bs[GBK][GBN + GPAD];

    const int tid = threadIdx.x;
    const int bm = blockIdx.y * GBM;
    const int bn = blockIdx.x * GBN;
    const int tx = tid & 15;
    const int ty = tid >> 4;

    float acc[GTM][GTN];
#pragma unroll
    for (int i = 0; i < GTM; i++)
#pragma unroll
        for (int j = 0; j < GTN; j++) acc[i][j] = 0.f;

    for (int k0 = 0; k0 < K; k0 += GBK) {
#pragma unroll
        for (int it = 0; it < 2; it++) {
            int i4 = tid + it * 256;
            int r  = i4 >> 2;
            int c  = (i4 & 3) << 2;
            float4 v = *(const float4*)&A[(size_t)(bm + r) * K + k0 + c];
            As[c + 0][r] = v.x; As[c + 1][r] = v.y;
            As[c + 2][r] = v.z; As[c + 3][r] = v.w;
        }
#pragma unroll
        for (int it = 0; it < 2; it++) {
            int i4 = tid + it * 256;
            int r  = i4 >> 2;
            int c  = (i4 & 3) << 2;
            float4 v = *(const float4*)&B[(size_t)(bn + r) * K + k0 + c];
            Bs[c + 0][r] = v.x; Bs[c + 1][r] = v.y;
            Bs[c + 2][r] = v.z; Bs[c + 3][r] = v.w;
        }
        __syncthreads();

#pragma unroll
        for (int kk = 0; kk < GBK; kk++) {
            float a[GTM], b[GTN];
#pragma unroll
            for (int i = 0; i < GTM; i++) a[i] = As[kk][ty * GTM + i];
#pragma unroll
            for (int j = 0; j < GTN; j++) b[j] = Bs[kk][tx * GTN + j];
#pragma unroll
            for (int i = 0; i < GTM; i++)
#pragma unroll
                for (int j = 0; j < GTN; j++)
                    acc[i][j] = fmaf(a[i], b[j], acc[i][j]);
        }
        __syncthreads();
    }

#pragma unroll
    for (int i = 0; i < GTM; i++) {
        int m = bm + ty * GTM + i;
        int n0 = bn + tx * GTN;
#pragma unroll
        for (int j = 0; j < GTN; j += 4) {
            float4 o;
            o.x = acc[i][j + 0] + bias[n0 + j + 0];
            o.y = acc[i][j + 1] + bias[n0 + j + 1];
            o.z = acc[i][j + 2] + bias[n0 + j + 2];
            o.w = acc[i][j + 3] + bias[n0 + j + 3];
            *(float4*)&C[(size_t)m * N + n0 + j] = o;
        }
    }
}

// ---------------------------------------------------------------------------
// Flash attention, fp32, register-tiled (GEMM-style) score and PV phases.
// Grid: (S/BM, NH). Block: 256 threads. One CTA: 64 queries of one head.
//
// Phase 1 (scores):  16x16 thread grid, 4 queries x 4 keys per thread.
//                    Qs/Ks stored transposed [d][row] so the d-loop reads
//                    float4 rows.
// Softmax:           4 threads per query row (16 keys each), shuffle-combined.
// Phase 3 (PV):      16x16 thread grid, 4 rows x 8 dims per thread with
//                    persistent accumulators rescaled via row_corr.
// ---------------------------------------------------------------------------
#define BM 64
#define BN 64
#define QST (BM + 4)     // 68: stride of transposed Q/K tiles
#define VST (HD + 4)     // 132
#define SST (BN + 4)     // 68

__global__ __launch_bounds__(256) void flash_attn_kernel(
    const float* __restrict__ Q, const float* __restrict__ K,
    const float* __restrict__ V, float* __restrict__ O)
{
    extern __shared__ float sm[];
    float* Qs = sm;                      // HD * QST   [d][q]
    float* Ks = Qs + HD * QST;           // HD * QST   [d][k]
    float* Vs = Ks + HD * QST;           // BN * VST   [k][d]
    float* Ss = Vs + BN * VST;           // BM * SST   [q][k]
    float* row_corr = Ss + BM * SST;     // BM
    float* row_l    = row_corr + BM;     // BM

    const int tid = threadIdx.x;
    const int h = blockIdx.y;
    const int qbase = blockIdx.x * BM;
    const size_t headoff = (size_t)h * HD;

    const int tx = tid & 15;   // phase-1: key group; phase-3: dim group
    const int ty = tid >> 4;   // phase-1: query group; phase-3: row group
    const int srow = tid >> 2; // softmax: query row
    const int scg  = tid & 3;  // softmax: key quarter

    // Load Q tile transposed + pre-scaled: Qs[d][q]
    for (int i = tid; i < BM * (HD / 4); i += 256) {
        int r = i / (HD / 4);
        int c = (i % (HD / 4)) * 4;
        float4 v = *(const float4*)&Q[(size_t)(qbase + r) * H + headoff + c];
        Qs[(c + 0) * QST + r] = v.x * SCALE;
        Qs[(c + 1) * QST + r] = v.y * SCALE;
        Qs[(c + 2) * QST + r] = v.z * SCALE;
        Qs[(c + 3) * QST + r] = v.w * SCALE;
    }

    float m_i = -INFINITY, l_i = 0.f;  // per softmax-thread row state
    float acc[4][8];
#pragma unroll
    for (int i = 0; i < 4; i++)
#pragma unroll
        for (int j = 0; j < 8; j++) acc[i][j] = 0.f;

    for (int kb = 0; kb < S; kb += BN) {
        __syncthreads();   // previous iteration done with Ks/Vs/Ss

        // Load K transposed [d][k], V row-major [k][d]
        for (int i = tid; i < BN * (HD / 4); i += 256) {
            int r = i / (HD / 4);
            int c = (i % (HD / 4)) * 4;
            float4 kv = *(const float4*)&K[(size_t)(kb + r) * H + headoff + c];
            Ks[(c + 0) * QST + r] = kv.x;
            Ks[(c + 1) * QST + r] = kv.y;
            Ks[(c + 2) * QST + r] = kv.z;
            Ks[(c + 3) * QST + r] = kv.w;
            float4 vv = *(const float4*)&V[(size_t)(kb + r) * H + headoff + c];
            *(float4*)&Vs[r * VST + c] = vv;
        }
        __syncthreads();

        // ---- Phase 1: S = Q K^T, 4x4 microtile ----
        float sacc[4][4];
#pragma unroll
        for (int i = 0; i < 4; i++)
#pragma unroll
            for (int j = 0; j < 4; j++) sacc[i][j] = 0.f;

#pragma unroll 8
        for (int d = 0; d < HD; d++) {
            float4 a = *(const float4*)&Qs[d * QST + ty * 4];
            float4 b = *(const float4*)&Ks[d * QST + tx * 4];
            float av[4] = {a.x, a.y, a.z, a.w};
            float bv[4] = {b.x, b.y, b.z, b.w};
#pragma unroll
            for (int i = 0; i < 4; i++)
#pragma unroll
                for (int j = 0; j < 4; j++)
                    sacc[i][j] = fmaf(av[i], bv[j], sacc[i][j]);
        }
#pragma unroll
        for (int i = 0; i < 4; i++) {
            float4 o = make_float4(sacc[i][0], sacc[i][1], sacc[i][2], sacc[i][3]);
            *(float4*)&Ss[(ty * 4 + i) * SST + tx * 4] = o;
        }
        __syncthreads();

        // ---- Softmax (online): 4 threads per row, 16 keys each ----
        float sv[16];
        float lmax = -INFINITY;
#pragma unroll
        for (int j = 0; j < 16; j++) {
            sv[j] = Ss[srow * SST + scg * 16 + j];
            lmax = fmaxf(lmax, sv[j]);
        }
        lmax = fmaxf(lmax, __shfl_xor_sync(0xffffffffu, lmax, 1));
        lmax = fmaxf(lmax, __shfl_xor_sync(0xffffffffu, lmax, 2));
        float m_new = fmaxf(m_i, lmax);
        float corr = __expf(m_i - m_new);
        float lsum = 0.f;
#pragma unroll
        for (int j = 0; j < 16; j++) {
            float p = __expf(sv[j] - m_new);
            Ss[srow * SST + scg * 16 + j] = p;
            lsum += p;
        }
        lsum += __shfl_xor_sync(0xffffffffu, lsum, 1);
        lsum += __shfl_xor_sync(0xffffffffu, lsum, 2);
        l_i = l_i * corr + lsum;
        m_i = m_new;
        if (scg == 0) {
            row_corr[srow] = corr;
            row_l[srow] = l_i;
        }
        __syncthreads();

        // ---- Phase 3: O += P V, 4x8 microtile, persistent acc ----
        float rc[4];
#pragma unroll
        for (int i = 0; i < 4; i++) rc[i] = row_corr[ty * 4 + i];
#pragma unroll
        for (int i = 0; i < 4; i++)
#pragma unroll
            for (int j = 0; j < 8; j++) acc[i][j] *= rc[i];

#pragma unroll 4
        for (int k = 0; k < BN; k++) {
            float4 b0 = *(const float4*)&Vs[k * VST + tx * 8];
            float4 b1 = *(const float4*)&Vs[k * VST + tx * 8 + 4];
            float bv[8] = {b0.x, b0.y, b0.z, b0.w, b1.x, b1.y, b1.z, b1.w};
            float av[4];
#pragma unroll
            for (int i = 0; i < 4; i++) av[i] = Ss[(ty * 4 + i) * SST + k];
#pragma unroll
            for (int i = 0; i < 4; i++)
#pragma unroll
                for (int j = 0; j < 8; j++)
                    acc[i][j] = fmaf(av[i], bv[j], acc[i][j]);
        }
    }

    // ---- Epilogue: normalize and write O ----
#pragma unroll
    for (int i = 0; i < 4; i++) {
        float inv = 1.f / row_l[ty * 4 + i];
        float* op = &O[(size_t)(qbase + ty * 4 + i) * H + headoff + tx * 8];
        float4 o0, o1;
        o0.x = acc[i][0] * inv; o0.y = acc[i][1] * inv;
        o0.z = acc[i][2] * inv; o0.w = acc[i][3] * inv;
        o1.x = acc[i][4] * inv; o1.y = acc[i][5] * inv;
        o1.z = acc[i][6] * inv; o1.w = acc[i][7] * inv;
        *(float4*)&op[0] = o0;
        *(float4*)&op[4] = o1;
    }
}

// ---------------------------------------------------------------------------
// Launch
// ---------------------------------------------------------------------------
extern "C" void kernel_launch(void* const* d_in, const int* in_sizes, int n_in,
                              void* d_out, int out_size)
{
    const float* hidden = (const float*)d_in[0];
    const float* Wq = (const float*)d_in[1];
    const float* bq = (const float*)d_in[2];
    const float* Wk = (const float*)d_in[3];
    const float* bk = (const float*)d_in[4];
    const float* Wv = (const float*)d_in[5];
    const float* bv = (const float*)d_in[6];
    const float* Wo = (const float*)d_in[7];
    const float* bo = (const float*)d_in[8];
    float* out = (float*)d_out;

    float *Qp, *Kp, *Vp, *Op;
    cudaGetSymbolAddress((void**)&Qp, g_Q);
    cudaGetSymbolAddress((void**)&Kp, g_K);
    cudaGetSymbolAddress((void**)&Vp, g_V);
    cudaGetSymbolAddress((void**)&Op, g_O);

    const int attn_smem = (int)((2 * HD * QST + BN * VST + BM * SST + 2 * BM)
                                * sizeof(float));
    cudaFuncSetAttribute(flash_attn_kernel,
                         cudaFuncAttributeMaxDynamicSharedMemorySize, attn_smem);

    dim3 ggrid(H / GBN, S / GBM);   // (16, 32)
    dim3 gblk(256);

    gemm_nt_bias<<<ggrid, gblk>>>(hidden, Wq, bq, Qp, S, H, H);
    gemm_nt_bias<<<ggrid, gblk>>>(hidden, Wk, bk, Kp, S, H, H);
    gemm_nt_bias<<<ggrid, gblk>>>(hidden, Wv, bv, Vp, S, H, H);

    dim3 agrid(S / BM, NH);         // (64, 16)
    flash_attn_kernel<<<agrid, 256, attn_smem>>>(Qp, Kp, Vp, Op);

    gemm_nt_bias<<<ggrid, gblk>>>(Op, Wo, bo, out, S, H, H);
}